// round 3
// baseline (speedup 1.0000x reference)
#include <cuda_runtime.h>
#include <math.h>

// Problem constants (fixed by weight shapes in this dataset)
#define RINGL 256
#define DD    128
#define INF   64
#define SDD   42
#define G3D   126   // 3*SD
#define NCLS  1000
#define NTHR  128

// ---------------- shared memory layout (floats) ----------------
__host__ __device__ constexpr int al4(int x) { return (x + 3) & ~3; }

constexpr int OFF_RING  = 0;                                  // 256*128
constexpr int OFF_WPROJ = al4(OFF_RING  + RINGL * DD);        // [42][65] padded
constexpr int OFF_WIH   = al4(OFF_WPROJ + SDD * 65);          // [126][43]
constexpr int OFF_WHH   = al4(OFF_WIH   + G3D * 43);          // [126][43]
constexpr int OFF_WBR   = al4(OFF_WHH   + G3D * 43);          // [128][43]
constexpr int OFF_WJ    = al4(OFF_WBR   + DD * 43);           // 128
constexpr int OFF_WG    = al4(OFF_WJ    + DD);                // 128
constexpr int OFF_BPROJ = al4(OFF_WG    + DD);                // 42
constexpr int OFF_BIH   = al4(OFF_BPROJ + SDD);               // 126
constexpr int OFF_BHH   = al4(OFF_BIH   + G3D);               // 126
constexpr int OFF_BBR   = al4(OFF_BHH   + G3D);               // 128
constexpr int OFF_XS    = al4(OFF_BBR   + DD);                // 64
constexpr int OFF_S     = al4(OFF_XS    + INF);               // 42
constexpr int OFF_H     = al4(OFF_S     + SDD);               // 42
constexpr int OFF_GX    = al4(OFF_H     + SDD);               // 126
constexpr int OFF_GH    = al4(OFF_GX    + G3D);               // 126
constexpr int OFF_RS    = al4(OFF_GH    + G3D);               // 128
constexpr int OFF_RED   = al4(OFF_RS    + DD);                // 8
constexpr int SMEM_FLTS = al4(OFF_RED   + 8);
constexpr int SMEM_BYTES = SMEM_FLTS * 4;                     // ~212 KB

// ---------------- XLA-matching math ----------------
// XLA:GPU f32 tanh: Eigen-style rational approximation
__device__ __forceinline__ float xla_tanh(float x) {
    float ax = fabsf(x);
    if (ax < 0.0004f) return x;
    float xc = fminf(fmaxf(x, -7.90531110763549805f), 7.90531110763549805f);
    float x2 = xc * xc;
    float num = fmaf(x2, fmaf(x2, fmaf(x2, fmaf(x2, fmaf(x2,
                    fmaf(x2, -2.76076847742355e-16f, 2.00018790482477e-13f),
                    -8.60467152213735e-11f), 5.12229709037114e-08f),
                    1.48572235717979e-05f), 6.37261928875436e-04f),
                    4.89352455891786e-03f);
    num *= xc;
    float den = fmaf(x2, fmaf(x2, fmaf(x2, 1.19825839466702e-06f,
                    1.18534705686654e-04f), 2.26843463243900e-03f),
                    4.89352518554385e-03f);
    return __fdiv_rn(num, den);
}
// XLA logistic_expander: sigmoid(x) = 0.5 + 0.5*tanh(0.5*x)
__device__ __forceinline__ float xla_sigmoid(float x) {
    return fmaf(0.5f, xla_tanh(0.5f * x), 0.5f);
}
// jnp.mod(v, 256) = v - 256*floor(v/256)   (1/256 is exact)
__device__ __forceinline__ float mod256(float v) {
    return v - 256.0f * floorf(v * (1.0f / 256.0f));
}
// Gaussian 5-tap soft window (jax.nn.softmax of -(d^2)/8 with max-subtraction)
__device__ __forceinline__ void soft_kernel(float ptr, int* pos, float* w) {
    float base = floorf(ptr);
    float frac = ptr - base;
    int ib = (int)base;
    float v[5], m = -1e30f;
#pragma unroll
    for (int k = 0; k < 5; k++) {
        float dd = (float)(k - 2) - frac;
        v[k] = -(dd * dd) * 0.125f;
        m = fmaxf(m, v[k]);
        pos[k] = (ib + k - 2 + RINGL) & (RINGL - 1);
    }
    float ssum = 0.0f;
#pragma unroll
    for (int k = 0; k < 5; k++) { w[k] = expf(v[k] - m); ssum += w[k]; }
#pragma unroll
    for (int k = 0; k < 5; k++) w[k] = __fdiv_rn(w[k], ssum);
}

// ---------------- main kernel: one CTA per batch element ----------------
__global__ void __launch_bounds__(NTHR, 1)
hallway_main(const float* __restrict__ x, const float* __restrict__ theta,
             const float* __restrict__ w_proj, const float* __restrict__ b_proj,
             const float* __restrict__ w_ih, const float* __restrict__ w_hh,
             const float* __restrict__ b_ih, const float* __restrict__ b_hh,
             const float* __restrict__ w_bridge, const float* __restrict__ b_bridge,
             const float* __restrict__ w_jump, const float* __restrict__ b_jump,
             const float* __restrict__ w_gate, const float* __restrict__ b_gate,
             const float* __restrict__ w_cls, const float* __restrict__ b_cls,
             float* __restrict__ out, int T)
{
    extern __shared__ float sm[];
    const int tid  = threadIdx.x;
    const int b    = blockIdx.x;
    const int lane = tid & 31;
    const int wid  = tid >> 5;

    // zero ring
    float4* ring4 = (float4*)(sm + OFF_RING);
#pragma unroll 8
    for (int i = tid; i < RINGL * DD / 4; i += NTHR) ring4[i] = make_float4(0.f, 0.f, 0.f, 0.f);

    // stage weights into padded SMEM (conflict-free strides 65 / 43)
    for (int i = tid; i < SDD * INF; i += NTHR) sm[OFF_WPROJ + (i / INF) * 65 + (i % INF)] = w_proj[i];
    for (int i = tid; i < G3D * SDD; i += NTHR) sm[OFF_WIH + (i / SDD) * 43 + (i % SDD)] = w_ih[i];
    for (int i = tid; i < G3D * SDD; i += NTHR) sm[OFF_WHH + (i / SDD) * 43 + (i % SDD)] = w_hh[i];
    for (int i = tid; i < DD * SDD;  i += NTHR) sm[OFF_WBR + (i / SDD) * 43 + (i % SDD)] = w_bridge[i];
    sm[OFF_WJ + tid] = w_jump[tid];
    sm[OFF_WG + tid] = w_gate[tid];
    if (tid < SDD) sm[OFF_BPROJ + tid] = b_proj[tid];
    if (tid < G3D) { sm[OFF_BIH + tid] = b_ih[tid]; sm[OFF_BHH + tid] = b_hh[tid]; }
    sm[OFF_BBR + tid] = b_bridge[tid];
    if (tid < SDD) sm[OFF_H + tid] = 0.0f;

    const float bj = b_jump[0];
    const float bg = b_gate[0];
    float ptr = mod256(theta[0]);

    const float* __restrict__ xb = x + (size_t)b * (size_t)T * INF + tid;
    const float* __restrict__ xs = sm + OFF_XS;
    const float* __restrict__ hs = sm + OFF_H;

    // stage x_0 directly; prefetch x_1 into register
    if (tid < INF) sm[OFF_XS + tid] = __ldg(xb);
    float xreg = (tid < INF) ? __ldg(xb + INF) : 0.0f;
    __syncthreads();

    for (int t = 0; t < T; ++t) {
        // ---------------- Phase A ----------------
        // soft read at old ptr + jump/gate reduction; s-projection overlapped
        int pos[5]; float w[5];
        soft_kernel(ptr, pos, w);
        float rd = 0.0f;
#pragma unroll
        for (int k = 0; k < 5; k++) rd = fmaf(w[k], sm[OFF_RING + pos[k] * DD + tid], rd);
        float pj = rd * sm[OFF_WJ + tid];
        float pg = rd * sm[OFF_WG + tid];
#pragma unroll
        for (int o = 16; o > 0; o >>= 1) {
            pj += __shfl_xor_sync(0xffffffffu, pj, o);
            pg += __shfl_xor_sync(0xffffffffu, pg, o);
        }
        if (lane == 0) { sm[OFF_RED + wid] = pj; sm[OFF_RED + 4 + wid] = pg; }

        // s = x_t @ w_proj^T + b_proj (independent of ring/ptr; overlaps above)
        if (tid < SDD) {
            const float* wr = sm + OFF_WPROJ + tid * 65;
            float a0 = 0.f, a1 = 0.f, a2 = 0.f, a3 = 0.f;
#pragma unroll
            for (int k = 0; k < INF; k += 4) {
                a0 = fmaf(wr[k],     xs[k],     a0);
                a1 = fmaf(wr[k + 1], xs[k + 1], a1);
                a2 = fmaf(wr[k + 2], xs[k + 2], a2);
                a3 = fmaf(wr[k + 3], xs[k + 3], a3);
            }
            sm[OFF_S + tid] = (a0 + a1) + (a2 + a3) + sm[OFF_BPROJ + tid];
        }
        __syncthreads();                                    // bar1: partials + s ready

        // ---------------- Phase B ----------------
        // pointer update — identical on every thread (deterministic)
        float jl = (sm[OFF_RED + 0] + sm[OFF_RED + 1]) + (sm[OFF_RED + 2] + sm[OFF_RED + 3]) + bj;
        float gl = (sm[OFF_RED + 4] + sm[OFF_RED + 5]) + (sm[OFF_RED + 6] + sm[OFF_RED + 7]) + bg;
        float jump = xla_sigmoid(jl) * 256.0f;
        float gate = xla_sigmoid(gl);
        float delta = mod256(jump - ptr + 128.0f) - 128.0f;
        float ptr_new = mod256(ptr + gate * delta);

        // stage x_{t+1} (x_t already consumed by s); prefetch x_{t+2}
        if (tid < INF) {
            sm[OFF_XS + tid] = xreg;
            if (t + 2 < T) xreg = __ldg(xb + (size_t)(t + 2) * INF);
        }

        // gx = s @ w_ih^T + b_ih ;  gh = h @ w_hh^T + b_hh
        if (tid < G3D) {
            const float* wi = sm + OFF_WIH + tid * 43;
            const float* wh = sm + OFF_WHH + tid * 43;
            float a0 = 0.f, a1 = 0.f, c0 = 0.f, c1 = 0.f;
#pragma unroll
            for (int k = 0; k < SDD; k += 2) {
                a0 = fmaf(wi[k],     sm[OFF_S + k],     a0);
                a1 = fmaf(wi[k + 1], sm[OFF_S + k + 1], a1);
                c0 = fmaf(wh[k],     hs[k],     c0);
                c1 = fmaf(wh[k + 1], hs[k + 1], c1);
            }
            sm[OFF_GX + tid] = a0 + a1 + sm[OFF_BIH + tid];
            sm[OFF_GH + tid] = c0 + c1 + sm[OFF_BHH + tid];
        }
        __syncthreads();                                    // bar2: gx/gh ready

        // ---------------- Phase C ----------------
        if (tid < SDD) {
            float rg = xla_sigmoid(sm[OFF_GX + tid] + sm[OFF_GH + tid]);
            float zg = xla_sigmoid(sm[OFF_GX + SDD + tid] + sm[OFF_GH + SDD + tid]);
            float ng = xla_tanh(fmaf(rg, sm[OFF_GH + 2 * SDD + tid], sm[OFF_GX + 2 * SDD + tid]));
            float hv = sm[OFF_H + tid];
            sm[OFF_H + tid] = (1.0f - zg) * ng + zg * hv;
        }
        __syncthreads();                                    // bar3: h ready

        // ---------------- Phase D ----------------
        // u = tanh(h @ w_bridge^T + b) ; soft write at new ptr
        {
            const float* wb = sm + OFF_WBR + tid * 43;
            float a0 = 0.f, a1 = 0.f, a2 = 0.f;
#pragma unroll
            for (int k = 0; k < SDD; k += 3) {
                a0 = fmaf(wb[k],     hs[k],     a0);
                a1 = fmaf(wb[k + 1], hs[k + 1], a1);
                a2 = fmaf(wb[k + 2], hs[k + 2], a2);
            }
            float uv = xla_tanh(a0 + a1 + a2 + sm[OFF_BBR + tid]);

            int pos2[5]; float w2[5];
            soft_kernel(ptr_new, pos2, w2);
#pragma unroll
            for (int k = 0; k < 5; k++) {
                float* p = sm + OFF_RING + pos2[k] * DD + tid;
                *p = fmaf(w2[k], uv, *p);
            }
        }
        ptr = ptr_new;
        __syncthreads();                                    // bar4: ring write + x stage visible
    }

    // --- final read ---
    {
        int pos[5]; float w[5];
        soft_kernel(ptr, pos, w);
        float rd = 0.0f;
#pragma unroll
        for (int k = 0; k < 5; k++) rd = fmaf(w[k], sm[OFF_RING + pos[k] * DD + tid], rd);
        sm[OFF_RS + tid] = rd;
    }
    __syncthreads();

    // --- classifier: out[b, :] = r @ w_cls^T + b_cls (L2-resident w_cls) ---
    float* ob = out + (size_t)b * NCLS;
    const float4* rr = (const float4*)(sm + OFF_RS);
    for (int c = tid; c < NCLS; c += NTHR) {
        const float4* wr = (const float4*)(w_cls + (size_t)c * DD);
        float a0 = 0.f, a1 = 0.f, a2 = 0.f, a3 = 0.f;
#pragma unroll
        for (int k = 0; k < DD / 4; k++) {
            float4 wv = __ldg(wr + k);
            float4 rv = rr[k];
            a0 = fmaf(wv.x, rv.x, a0);
            a1 = fmaf(wv.y, rv.y, a1);
            a2 = fmaf(wv.z, rv.z, a2);
            a3 = fmaf(wv.w, rv.w, a3);
        }
        ob[c] = (a0 + a1) + (a2 + a3) + b_cls[c];
    }
}

extern "C" void kernel_launch(void* const* d_in, const int* in_sizes, int n_in,
                              void* d_out, int out_size)
{
    const float* x        = (const float*)d_in[0];
    const float* theta    = (const float*)d_in[1];
    const float* w_proj   = (const float*)d_in[2];
    const float* b_proj   = (const float*)d_in[3];
    const float* w_ih     = (const float*)d_in[4];
    const float* w_hh     = (const float*)d_in[5];
    const float* b_ih     = (const float*)d_in[6];
    const float* b_hh     = (const float*)d_in[7];
    const float* w_bridge = (const float*)d_in[8];
    const float* b_bridge = (const float*)d_in[9];
    const float* w_jump   = (const float*)d_in[10];
    const float* b_jump   = (const float*)d_in[11];
    const float* w_gate   = (const float*)d_in[12];
    const float* b_gate   = (const float*)d_in[13];
    const float* w_cls    = (const float*)d_in[14];
    const float* b_cls    = (const float*)d_in[15];
    float* out = (float*)d_out;

    int B = out_size / NCLS;
    int T = in_sizes[0] / (B * INF);

    cudaFuncSetAttribute(hallway_main, cudaFuncAttributeMaxDynamicSharedMemorySize, SMEM_BYTES);
    hallway_main<<<B, NTHR, SMEM_BYTES>>>(x, theta, w_proj, b_proj, w_ih, w_hh,
                                          b_ih, b_hh, w_bridge, b_bridge,
                                          w_jump, b_jump, w_gate, b_gate,
                                          w_cls, b_cls, out, T);
}

// round 17
// speedup vs baseline: 1.0318x; 1.0318x over previous
#include <cuda_runtime.h>
#include <math.h>

// Problem constants (fixed by weight shapes in this dataset)
#define RINGL 256
#define DD    128
#define INF   64
#define SDD   42
#define G3D   126   // 3*SD
#define NCLS  1000
#define NTHR  384

// ---------------- shared memory layout (floats) ----------------
// Strides chosen conflict-free for the access patterns:
//  wproj stride 68 (=4 mod 32): 8-lane LDS.128 phases cover all 32 banks
//  wih/whh stride 44 (=12 mod 32): same property
//  wbridge stride 43 (odd): conflict-free scalar loads
__host__ __device__ constexpr int al4(int x) { return (x + 3) & ~3; }

constexpr int OFF_RING  = 0;                                   // 256*128
constexpr int OFF_WPJ   = 32768;                               // [42][68]
constexpr int OFF_WIH   = al4(OFF_WPJ + SDD * 68);             // [126][44]
constexpr int OFF_WHH   = al4(OFF_WIH + G3D * 44);             // [126][44]
constexpr int OFF_WBR   = al4(OFF_WHH + G3D * 44);             // [128][43]
constexpr int OFF_XS    = al4(OFF_WBR + DD * 43);              // 64
constexpr int OFF_SS    = OFF_XS + 64;                         // 42 (+2 pad)
constexpr int OFF_HH    = OFF_SS + 44;                         // 42 (+2 pad)
constexpr int OFF_WJ    = OFF_HH + 44;                         // 128
constexpr int OFF_WG    = OFF_WJ + 128;                        // 128
constexpr int OFF_BPROJ = OFF_WG + 128;                        // 42 (+2)
constexpr int OFF_BIH   = OFF_BPROJ + 44;                      // 126
constexpr int OFF_BHH   = OFF_BIH + G3D;                       // 126
constexpr int OFF_BBR   = OFF_BHH + G3D;                       // 128
constexpr int OFF_GX    = OFF_BBR + 128;                       // 126
constexpr int OFF_GH    = OFF_GX + G3D;                        // 126
constexpr int OFF_RED   = OFF_GH + G3D;                        // 8
constexpr int OFF_KW    = OFF_RED + 8;                         // 5 window weights
constexpr int OFF_KP    = OFF_KW + 5;                          // 5 window positions
constexpr int OFF_PTR   = OFF_KP + 5;                          // 1
constexpr int OFF_RS    = al4(OFF_PTR + 1);                    // 128
constexpr int SMEM_FLTS = OFF_RS + 128;
constexpr int SMEM_BYTES = SMEM_FLTS * 4;                      // ~214 KB

static_assert((OFF_WPJ & 3) == 0 && (OFF_WIH & 3) == 0 && (OFF_WHH & 3) == 0, "w align");
static_assert((OFF_XS & 3) == 0 && (OFF_SS & 3) == 0 && (OFF_HH & 3) == 0, "v align");
static_assert((OFF_RS & 3) == 0, "rs align");
static_assert(SMEM_BYTES <= 232448, "smem budget");

// ---------------- XLA-matching math (identical to the R3 passing kernel) ----------------
__device__ __forceinline__ float xla_tanh(float x) {
    float ax = fabsf(x);
    if (ax < 0.0004f) return x;
    float xc = fminf(fmaxf(x, -7.90531110763549805f), 7.90531110763549805f);
    float x2 = xc * xc;
    float num = fmaf(x2, fmaf(x2, fmaf(x2, fmaf(x2, fmaf(x2,
                    fmaf(x2, -2.76076847742355e-16f, 2.00018790482477e-13f),
                    -8.60467152213735e-11f), 5.12229709037114e-08f),
                    1.48572235717979e-05f), 6.37261928875436e-04f),
                    4.89352455891786e-03f);
    num *= xc;
    float den = fmaf(x2, fmaf(x2, fmaf(x2, 1.19825839466702e-06f,
                    1.18534705686654e-04f), 2.26843463243900e-03f),
                    4.89352518554385e-03f);
    return __fdiv_rn(num, den);
}
__device__ __forceinline__ float xla_sigmoid(float x) {
    return fmaf(0.5f, xla_tanh(0.5f * x), 0.5f);
}
__device__ __forceinline__ float mod256(float v) {
    return v - 256.0f * floorf(v * (1.0f / 256.0f));
}
__device__ __forceinline__ void soft_kernel(float ptr, int* pos, float* w) {
    float base = floorf(ptr);
    float frac = ptr - base;
    int ib = (int)base;
    float v[5], m = -1e30f;
#pragma unroll
    for (int k = 0; k < 5; k++) {
        float dd = (float)(k - 2) - frac;
        v[k] = -(dd * dd) * 0.125f;
        m = fmaxf(m, v[k]);
        pos[k] = (ib + k - 2 + RINGL) & (RINGL - 1);
    }
    float ssum = 0.0f;
#pragma unroll
    for (int k = 0; k < 5; k++) { w[k] = expf(v[k] - m); ssum += w[k]; }
#pragma unroll
    for (int k = 0; k < 5; k++) w[k] = __fdiv_rn(w[k], ssum);
}

// ---------------- main kernel: one CTA per batch element ----------------
__global__ void __launch_bounds__(NTHR, 1)
hallway_main(const float* __restrict__ x, const float* __restrict__ theta,
             const float* __restrict__ w_proj, const float* __restrict__ b_proj,
             const float* __restrict__ w_ih, const float* __restrict__ w_hh,
             const float* __restrict__ b_ih, const float* __restrict__ b_hh,
             const float* __restrict__ w_bridge, const float* __restrict__ b_bridge,
             const float* __restrict__ w_jump, const float* __restrict__ b_jump,
             const float* __restrict__ w_gate, const float* __restrict__ b_gate,
             const float* __restrict__ w_cls, const float* __restrict__ b_cls,
             float* __restrict__ out, int T)
{
    extern __shared__ float sm[];
    const int tid  = threadIdx.x;
    const int b    = blockIdx.x;
    const int lane = tid & 31;
    const int wid  = tid >> 5;

    // ---- init: zero ring ----
    float4* ring4 = (float4*)(sm + OFF_RING);
    for (int i = tid; i < RINGL * DD / 4; i += NTHR) ring4[i] = make_float4(0.f, 0.f, 0.f, 0.f);

    // ---- stage weights (padded strides) ----
    for (int i = tid; i < SDD * INF; i += NTHR) sm[OFF_WPJ + (i / INF) * 68 + (i % INF)] = w_proj[i];
    for (int i = tid; i < G3D * SDD; i += NTHR) sm[OFF_WIH + (i / SDD) * 44 + (i % SDD)] = w_ih[i];
    for (int i = tid; i < G3D * SDD; i += NTHR) sm[OFF_WHH + (i / SDD) * 44 + (i % SDD)] = w_hh[i];
    for (int i = tid; i < DD * SDD;  i += NTHR) sm[OFF_WBR + (i / SDD) * 43 + (i % SDD)] = w_bridge[i];
    if (tid < DD)  { sm[OFF_WJ + tid] = w_jump[tid]; sm[OFF_WG + tid] = w_gate[tid]; }
    if (tid < SDD) sm[OFF_BPROJ + tid] = b_proj[tid];
    if (tid < G3D) { sm[OFF_BIH + tid] = b_ih[tid]; sm[OFF_BHH + tid] = b_hh[tid]; }
    if (tid < DD)  sm[OFF_BBR + tid] = b_bridge[tid];
    if (tid < 44)  { sm[OFF_SS + tid] = 0.0f; sm[OFF_HH + tid] = 0.0f; }

    const float bj = b_jump[0];
    const float bg = b_gate[0];

    // ---- stage x_0; warp 9 prefetches x_1 ----
    const float4* xb4 = (const float4*)(x + (size_t)b * (size_t)T * INF);
    if (tid < 16) ((float4*)(sm + OFF_XS))[tid] = __ldg(xb4 + tid);
    float4 xv = make_float4(0.f, 0.f, 0.f, 0.f);
    if (wid == 9 && lane < 16 && T > 1) xv = __ldg(xb4 + 16 + lane);

    // initial pointer + soft window (thread 0)
    if (tid == 0) {
        float p0 = mod256(theta[0]);
        int kp[5]; float kw[5];
        soft_kernel(p0, kp, kw);
#pragma unroll
        for (int k = 0; k < 5; k++) {
            sm[OFF_KW + k] = kw[k];
            sm[OFF_KP + k] = __int_as_float(kp[k]);
        }
        sm[OFF_PTR] = p0;
    }
    float ptr_reg = mod256(theta[0]);   // live only in warp 8
    __syncthreads();

    for (int t = 0; t < T; ++t) {
        // ================= Phase A =================
        if (tid < 128) {
            // soft read at current ptr (window precomputed; bit-identical values)
            float kw[5]; int kp[5];
#pragma unroll
            for (int k = 0; k < 5; k++) {
                kw[k] = sm[OFF_KW + k];
                kp[k] = __float_as_int(sm[OFF_KP + k]);
            }
            float rd = 0.0f;
#pragma unroll
            for (int k = 0; k < 5; k++) rd = fmaf(kw[k], sm[OFF_RING + kp[k] * DD + tid], rd);
            float pj = rd * sm[OFF_WJ + tid];
            float pg = rd * sm[OFF_WG + tid];
#pragma unroll
            for (int o = 16; o > 0; o >>= 1) {
                pj += __shfl_xor_sync(0xffffffffu, pj, o);
                pg += __shfl_xor_sync(0xffffffffu, pg, o);
            }
            if (lane == 0) { sm[OFF_RED + wid] = pj; sm[OFF_RED + 4 + wid] = pg; }
        } else if (tid < 128 + SDD) {
            // s = x @ w_proj^T + b_proj : one thread per row, R3 accumulator pattern
            int r = tid - 128;
            const float* wr = sm + OFF_WPJ + r * 68;
            const float* xs = sm + OFF_XS;
            float a0 = 0.f, a1 = 0.f, a2 = 0.f, a3 = 0.f;
#pragma unroll
            for (int i = 0; i < 16; i++) {
                float4 a = *(const float4*)(wr + i * 4);
                float4 v = *(const float4*)(xs + i * 4);
                a0 = fmaf(a.x, v.x, a0);
                a1 = fmaf(a.y, v.y, a1);
                a2 = fmaf(a.z, v.z, a2);
                a3 = fmaf(a.w, v.w, a3);
            }
            sm[OFF_SS + r] = (a0 + a1) + (a2 + a3) + sm[OFF_BPROJ + r];
        }
        __syncthreads();                                    // bar1

        // ================= Phase B =================
        if (tid < G3D) {
            // gx/gh rows: one thread per row, R3 parity accumulators (a0 even k, a1 odd k)
            const float* wi = sm + OFF_WIH + tid * 44;
            const float* wh = sm + OFF_WHH + tid * 44;
            const float* sv = sm + OFF_SS;
            const float* hv = sm + OFF_HH;
            float a0 = 0.f, a1 = 0.f, c0 = 0.f, c1 = 0.f;
#pragma unroll
            for (int i = 0; i < 10; i++) {
                float4 a = *(const float4*)(wi + i * 4);
                float4 s4 = *(const float4*)(sv + i * 4);
                float4 c = *(const float4*)(wh + i * 4);
                float4 h4 = *(const float4*)(hv + i * 4);
                a0 = fmaf(a.x, s4.x, a0);
                a1 = fmaf(a.y, s4.y, a1);
                a0 = fmaf(a.z, s4.z, a0);
                a1 = fmaf(a.w, s4.w, a1);
                c0 = fmaf(c.x, h4.x, c0);
                c1 = fmaf(c.y, h4.y, c1);
                c0 = fmaf(c.z, h4.z, c0);
                c1 = fmaf(c.w, h4.w, c1);
            }
            a0 = fmaf(wi[40], sv[40], a0);
            a1 = fmaf(wi[41], sv[41], a1);
            c0 = fmaf(wh[40], hv[40], c0);
            c1 = fmaf(wh[41], hv[41], c1);
            sm[OFF_GX + tid] = a0 + a1 + sm[OFF_BIH + tid];
            sm[OFF_GH + tid] = c0 + c1 + sm[OFF_BHH + tid];
        } else if (wid == 8) {
            // pointer update + soft window for the NEW ptr (same exprs as R3)
            float jl = (sm[OFF_RED + 0] + sm[OFF_RED + 1]) + (sm[OFF_RED + 2] + sm[OFF_RED + 3]) + bj;
            float gl = (sm[OFF_RED + 4] + sm[OFF_RED + 5]) + (sm[OFF_RED + 6] + sm[OFF_RED + 7]) + bg;
            float jump = xla_sigmoid(jl) * 256.0f;
            float gate = xla_sigmoid(gl);
            float delta = mod256(jump - ptr_reg + 128.0f) - 128.0f;
            float pn = mod256(ptr_reg + gate * delta);
            ptr_reg = pn;
            int kp[5]; float kw[5];
            soft_kernel(pn, kp, kw);
            if (lane == 0) {
#pragma unroll
                for (int k = 0; k < 5; k++) {
                    sm[OFF_KW + k] = kw[k];
                    sm[OFF_KP + k] = __int_as_float(kp[k]);
                }
                sm[OFF_PTR] = pn;
            }
        } else if (wid == 9) {
            // stage x_{t+1}, prefetch x_{t+2}
            if (lane < 16) {
                if (t + 1 < T) ((float4*)(sm + OFF_XS))[lane] = xv;
                if (t + 2 < T) xv = __ldg(xb4 + (size_t)(t + 2) * 16 + lane);
            }
        }
        __syncthreads();                                    // bar2

        // ================= Phase C =================
        if (tid < SDD) {
            float rg = xla_sigmoid(sm[OFF_GX + tid] + sm[OFF_GH + tid]);
            float zg = xla_sigmoid(sm[OFF_GX + SDD + tid] + sm[OFF_GH + SDD + tid]);
            float ng = xla_tanh(fmaf(rg, sm[OFF_GH + 2 * SDD + tid], sm[OFF_GX + 2 * SDD + tid]));
            float hv = sm[OFF_HH + tid];
            sm[OFF_HH + tid] = (1.0f - zg) * ng + zg * hv;
        }
        __syncthreads();                                    // bar3

        // ================= Phase D =================
        if (tid < 256) {
            // row r = tid/2; even thread computes the dot with R3's 3-acc stride-3
            // pattern; uv is broadcast to the partner (value transport, no FP change)
            // and the 5 disjoint ring taps are split 3/2 across the pair.
            int r = tid >> 1, h = tid & 1;
            float uv = 0.0f;
            if (h == 0) {
                const float* wb = sm + OFF_WBR + r * 43;
                const float* hv = sm + OFF_HH;
                float a0 = 0.f, a1 = 0.f, a2 = 0.f;
#pragma unroll
                for (int k = 0; k < SDD; k += 3) {
                    a0 = fmaf(wb[k],     hv[k],     a0);
                    a1 = fmaf(wb[k + 1], hv[k + 1], a1);
                    a2 = fmaf(wb[k + 2], hv[k + 2], a2);
                }
                uv = xla_tanh(a0 + a1 + a2 + sm[OFF_BBR + r]);
            }
            float uvp = __shfl_xor_sync(0xffffffffu, uv, 1);
            if (h == 1) uv = uvp;

            float kw[5]; int kp[5];
#pragma unroll
            for (int k = 0; k < 5; k++) {
                kw[k] = sm[OFF_KW + k];
                kp[k] = __float_as_int(sm[OFF_KP + k]);
            }
            if (h == 0) {
#pragma unroll
                for (int k = 0; k < 3; k++) {
                    float* pp = sm + OFF_RING + kp[k] * DD + r;
                    *pp = fmaf(kw[k], uv, *pp);
                }
            } else {
#pragma unroll
                for (int k = 3; k < 5; k++) {
                    float* pp = sm + OFF_RING + kp[k] * DD + r;
                    *pp = fmaf(kw[k], uv, *pp);
                }
            }
        }
        __syncthreads();                                    // bar4
    }

    // ---- final read (window for final ptr already in smem) ----
    if (tid < 128) {
        float kw[5]; int kp[5];
#pragma unroll
        for (int k = 0; k < 5; k++) {
            kw[k] = sm[OFF_KW + k];
            kp[k] = __float_as_int(sm[OFF_KP + k]);
        }
        float rd = 0.0f;
#pragma unroll
        for (int k = 0; k < 5; k++) rd = fmaf(kw[k], sm[OFF_RING + kp[k] * DD + tid], rd);
        sm[OFF_RS + tid] = rd;
    }
    __syncthreads();

    // ---- classifier: out[b, :] = r @ w_cls^T + b_cls ----
    float* ob = out + (size_t)b * NCLS;
    const float4* rr = (const float4*)(sm + OFF_RS);
    for (int c = tid; c < NCLS; c += NTHR) {
        const float4* wr = (const float4*)(w_cls + (size_t)c * DD);
        float a0 = 0.f, a1 = 0.f, a2 = 0.f, a3 = 0.f;
#pragma unroll
        for (int k = 0; k < DD / 4; k++) {
            float4 wv = __ldg(wr + k);
            float4 rv = rr[k];
            a0 = fmaf(wv.x, rv.x, a0);
            a1 = fmaf(wv.y, rv.y, a1);
            a2 = fmaf(wv.z, rv.z, a2);
            a3 = fmaf(wv.w, rv.w, a3);
        }
        ob[c] = (a0 + a1) + (a2 + a3) + b_cls[c];
    }
}

extern "C" void kernel_launch(void* const* d_in, const int* in_sizes, int n_in,
                              void* d_out, int out_size)
{
    const float* x        = (const float*)d_in[0];
    const float* theta    = (const float*)d_in[1];
    const float* w_proj   = (const float*)d_in[2];
    const float* b_proj   = (const float*)d_in[3];
    const float* w_ih     = (const float*)d_in[4];
    const float* w_hh     = (const float*)d_in[5];
    const float* b_ih     = (const float*)d_in[6];
    const float* b_hh     = (const float*)d_in[7];
    const float* w_bridge = (const float*)d_in[8];
    const float* b_bridge = (const float*)d_in[9];
    const float* w_jump   = (const float*)d_in[10];
    const float* b_jump   = (const float*)d_in[11];
    const float* w_gate   = (const float*)d_in[12];
    const float* b_gate   = (const float*)d_in[13];
    const float* w_cls    = (const float*)d_in[14];
    const float* b_cls    = (const float*)d_in[15];
    float* out = (float*)d_out;

    int B = out_size / NCLS;
    int T = in_sizes[0] / (B * INF);

    cudaFuncSetAttribute(hallway_main, cudaFuncAttributeMaxDynamicSharedMemorySize, SMEM_BYTES);
    hallway_main<<<B, NTHR, SMEM_BYTES>>>(x, theta, w_proj, b_proj, w_ih, w_hh,
                                          b_ih, b_hh, w_bridge, b_bridge,
                                          w_jump, b_jump, w_gate, b_gate,
                                          w_cls, b_cls, out, T);
}